// round 8
// baseline (speedup 1.0000x reference)
#include <cuda_runtime.h>

#define BN    8
#define NPIX  (224*224)   // 50176
#define SS    196
#define EE    768
#define NBLK  98          // blocks per image in k_main
#define TPB   256         // threads per block in k_main
#define PXT   2           // pixels per thread  (98*256*2 = 50176 exactly)
#define ROWS_PER_BLK 16   // rows per k_out block; 1568/16 = 98 blocks

// Final accumulators. Zero-initialized at module load; k_out re-zeroes them
// after use so every kernel_launch call starts from zeros (graph-replay safe).
__device__ float g_sum[BN*SS];     // sum exp
__device__ float g_p0 [BN*SS];     // sum e*c0
__device__ float g_p1 [BN*SS];
__device__ float g_p2 [BN*SS];
__device__ int   g_cnt[BN*SS];     // pixel count

// Fused pass: 196-way argmax per pixel + exp(score); accumulation goes
// straight to L2 via no-return global reductions (REDG) -- the shared-memory
// atomic path was LSU-bound (~2 cyc/lane spread-ATOMS) and dominated runtime.
// Softmax shift-invariance => no max subtraction needed (scores are O(10)).
__global__ __launch_bounds__(TPB) void k_main(
        const float* __restrict__ img,
        const float* __restrict__ Wseg,
        const float* __restrict__ bseg,
        const float* __restrict__ wq){
    __shared__ float4 sW[SS];
    int t = threadIdx.x;
    if (t < SS)
        sW[t] = make_float4(Wseg[3*t], Wseg[3*t+1], Wseg[3*t+2], bseg[t]);
    __syncthreads();

    int b = blockIdx.y;
    const float* im = img + (size_t)b*3*NPIX;
    int n = (blockIdx.x*TPB + t)*PXT;          // 2 consecutive pixels

    float c0[PXT], c1[PXT], c2[PXT];
    {
        float2 u = *(const float2*)(im + n);
        float2 v = *(const float2*)(im + NPIX + n);
        float2 w = *(const float2*)(im + 2*NPIX + n);
        c0[0]=u.x; c0[1]=u.y;
        c1[0]=v.x; c1[1]=v.y;
        c2[0]=w.x; c2[1]=w.y;
    }

    float best[PXT]; int bi[PXT];
    #pragma unroll
    for (int p = 0; p < PXT; p++){ best[p] = -3.4e38f; bi[p] = 0; }

    #pragma unroll 7
    for (int s = 0; s < SS; s++){
        float4 w = sW[s];           // one broadcast LDS.128 per 2 px
        #pragma unroll
        for (int p = 0; p < PXT; p++){
            float l = fmaf(c0[p], w.x, fmaf(c1[p], w.y, fmaf(c2[p], w.z, w.w)));
            bool gt = (l > best[p]);          // strict > keeps lowest-index ties
            best[p] = gt ? l : best[p];
            bi[p]   = gt ? s : bi[p];
        }
    }

    float q0 = wq[0], q1 = wq[1], q2 = wq[2];
    #pragma unroll
    for (int p = 0; p < PXT; p++){
        float score = fmaf(c0[p], q0, fmaf(c1[p], q1, c2[p]*q2));
        float e = __expf(score);
        int bs = b*SS + bi[p];
        // results unused -> ptxas emits no-return RED.E.ADD at L2
        atomicAdd(&g_sum[bs], e);
        atomicAdd(&g_p0[bs],  e*c0[p]);
        atomicAdd(&g_p1[bs],  e*c1[p]);
        atomicAdd(&g_p2[bs],  e*c2[p]);
        atomicAdd(&g_cnt[bs], 1);
    }
}

// Project: 98 blocks x 256 threads, 16 rows each. No reduction needed --
// k_main already produced final sums. After consuming a row, zero its
// accumulators so the next kernel_launch call starts clean.
__global__ __launch_bounds__(256) void k_out(
        const float* __restrict__ Wout,
        const float* __restrict__ bout,
        float* __restrict__ out){
    __shared__ float4 sWo[EE];              // (w0,w1,w2,bias) -> 12 KB
    __shared__ float4 srow[ROWS_PER_BLK];   // (p0,p1,p2,biasScale)
    int t = threadIdx.x;

    for (int e = t; e < EE; e += 256)
        sWo[e] = make_float4(Wout[3*e], Wout[3*e+1], Wout[3*e+2], bout[e]);

    if (t < ROWS_PER_BLK){
        int bs = blockIdx.x*ROWS_PER_BLK + t;
        int   cnt  = g_cnt[bs];
        float vsum = g_sum[bs];
        float v0 = g_p0[bs], v1 = g_p1[bs], v2 = g_p2[bs];
        float4 rv = make_float4(0.f, 0.f, 0.f, 0.f);
        if (cnt > 0){
            float D   = vsum + (float)(NPIX - cnt);  // background exp(0)=1 terms
            float inv = 1.0f / D;
            rv = make_float4(v0*inv, v1*inv, v2*inv, 1.0f);
        }
        srow[t] = rv;
        // reset for the next call (deterministic across graph replays)
        g_sum[bs] = 0.f; g_p0[bs] = 0.f; g_p1[bs] = 0.f; g_p2[bs] = 0.f;
        g_cnt[bs] = 0;
    }
    __syncthreads();

    #pragma unroll
    for (int r = 0; r < ROWS_PER_BLK; r++){
        float4 p = srow[r];
        float* o = out + (size_t)(blockIdx.x*ROWS_PER_BLK + r)*EE;
        #pragma unroll
        for (int e = t; e < EE; e += 256){
            float4 wv = sWo[e];
            // invalid row => p = (0,0,0,0) -> exact 0 (bias suppressed)
            o[e] = fmaf(p.x, wv.x, fmaf(p.y, wv.y, fmaf(p.z, wv.z, p.w*wv.w)));
        }
    }
}

extern "C" void kernel_launch(void* const* d_in, const int* in_sizes, int n_in,
                              void* d_out, int out_size) {
    const float* img  = (const float*)d_in[0];   // [8,3,224,224]
    const float* Wseg = (const float*)d_in[1];   // [196,3]
    const float* bseg = (const float*)d_in[2];   // [196]
    const float* wq   = (const float*)d_in[3];   // [3]
    const float* Wout = (const float*)d_in[4];   // [768,3]
    const float* bout = (const float*)d_in[5];   // [768]
    float* out = (float*)d_out;                  // [8,196,768]

    dim3 g(NBLK, BN);                            // 784 blocks, 256 thr
    k_main<<<g, TPB>>>(img, Wseg, bseg, wq);
    k_out<<<(BN*SS)/ROWS_PER_BLK, 256>>>(Wout, bout, out);  // 98 blocks
}

// round 9
// speedup vs baseline: 1.6356x; 1.6356x over previous
#include <cuda_runtime.h>

typedef unsigned long long ull;

#define BN    8
#define NPIX  (224*224)   // 50176
#define SS    196
#define EE    768
#define NBLK  98          // blocks per image in k_main
#define TPB   256         // threads per block
#define OROWS 8           // rows per k_out block; 1568/8 = 196 blocks

// Final accumulators. Zero-initialized at load; k_out re-zeroes after use so
// every kernel_launch call (and every graph replay) starts from zeros.
__device__ float g_sum[BN*SS];   // sum (e - 1)   -> D = NPIX + g_sum
__device__ float g_p0 [BN*SS];   // sum e*c0
__device__ float g_p1 [BN*SS];
__device__ float g_p2 [BN*SS];

__device__ __forceinline__ ull ffma2(ull a, ull b, ull c){
    ull d;
    asm("fma.rn.f32x2 %0, %1, %2, %3;" : "=l"(d) : "l"(a), "l"(b), "l"(c));
    return d;
}

// Fused pass: per-pixel 196-way argmax + exp(score), smem segmented
// accumulation, per-block flush via no-return global RED.
// Argmax trick: clear low 8 mantissa bits of each logit and embed the segment
// index there; a plain fmaxf chain then carries the winning index along.
// (Perturbs logits by <=2^-15 relative -> only near-ties can flip; harmless
// at rel_err 1e-3.) Both pixels of a thread share one packed f32x2 FMA chain.
__global__ __launch_bounds__(TPB) void k_main(
        const float* __restrict__ img,
        const float* __restrict__ Wseg,
        const float* __restrict__ bseg,
        const float* __restrict__ wq){
    __shared__ __align__(16) float sWp[SS*8];  // per s: wx,wx,wy,wy,wz,wz,wb,wb
    __shared__ float sSum[SS], sP0[SS], sP1[SS], sP2[SS];
    int t = threadIdx.x;
    if (t < SS){
        float wx = Wseg[3*t], wy = Wseg[3*t+1], wz = Wseg[3*t+2], wb = bseg[t];
        float* d = &sWp[t*8];
        d[0]=wx; d[1]=wx; d[2]=wy; d[3]=wy; d[4]=wz; d[5]=wz; d[6]=wb; d[7]=wb;
        sSum[t]=0.f; sP0[t]=0.f; sP1[t]=0.f; sP2[t]=0.f;
    }
    __syncthreads();

    int b = blockIdx.y;
    const float* im = img + (size_t)b*3*NPIX;
    int n = (blockIdx.x*TPB + t)*2;            // 2 consecutive pixels

    ull A = *(const ull*)(im + n);             // (c0[0], c0[1])
    ull B = *(const ull*)(im + NPIX + n);      // (c1[0], c1[1])
    ull C = *(const ull*)(im + 2*NPIX + n);    // (c2[0], c2[1])

    float best0 = -3.4e38f, best1 = -3.4e38f;
    #pragma unroll 4
    for (int s = 0; s < SS; s++){
        ulonglong2 qa = *(const ulonglong2*)&sWp[s*8];     // (wx,wx),(wy,wy)
        ulonglong2 qb = *(const ulonglong2*)&sWp[s*8 + 4]; // (wz,wz),(wb,wb)
        ull l = ffma2(A, qa.x, qb.y);          // c0*wx + wb
        l = ffma2(B, qa.y, l);                 // + c1*wy
        l = ffma2(C, qb.x, l);                 // + c2*wz
        unsigned lo = (unsigned)l, hi = (unsigned)(l >> 32);
        lo = (lo & 0xFFFFFF00u) | (unsigned)s;  // single LOP3 each
        hi = (hi & 0xFFFFFF00u) | (unsigned)s;
        best0 = fmaxf(best0, __uint_as_float(lo));
        best1 = fmaxf(best1, __uint_as_float(hi));
    }
    int bi0 = __float_as_uint(best0) & 0xFFu;
    int bi1 = __float_as_uint(best1) & 0xFFu;

    float c00 = __uint_as_float((unsigned)A), c01 = __uint_as_float((unsigned)(A>>32));
    float c10 = __uint_as_float((unsigned)B), c11 = __uint_as_float((unsigned)(B>>32));
    float c20 = __uint_as_float((unsigned)C), c21 = __uint_as_float((unsigned)(C>>32));
    float q0 = wq[0], q1 = wq[1], q2 = wq[2];

    float e0 = __expf(fmaf(c00, q0, fmaf(c10, q1, c20*q2)));
    float e1 = __expf(fmaf(c01, q0, fmaf(c11, q1, c21*q2)));

    atomicAdd(&sSum[bi0], e0 - 1.0f);
    atomicAdd(&sP0[bi0], e0*c00);
    atomicAdd(&sP1[bi0], e0*c10);
    atomicAdd(&sP2[bi0], e0*c20);

    atomicAdd(&sSum[bi1], e1 - 1.0f);
    atomicAdd(&sP0[bi1], e1*c01);
    atomicAdd(&sP1[bi1], e1*c11);
    atomicAdd(&sP2[bi1], e1*c21);
    __syncthreads();

    // flush: no-return global REDs; only 98 ops per address -> low contention
    if (t < SS){
        int bs = b*SS + t;
        atomicAdd(&g_sum[bs], sSum[t]);
        atomicAdd(&g_p0[bs],  sP0[t]);
        atomicAdd(&g_p1[bs],  sP1[t]);
        atomicAdd(&g_p2[bs],  sP2[t]);
    }
}

// Project: 196 blocks x 128 threads, 8 rows each; Wout held in registers
// (6 e-values per thread), stores coalesced. Resets accumulators after use.
__global__ __launch_bounds__(128) void k_out(
        const float* __restrict__ Wout,
        const float* __restrict__ bout,
        float* __restrict__ out){
    __shared__ float4 srow[OROWS];          // (p0,p1,p2,biasScale)
    int t = threadIdx.x;

    float w0[6], w1[6], w2[6], bb[6];
    #pragma unroll
    for (int k = 0; k < 6; k++){
        int e = t + k*128;
        w0[k] = Wout[3*e]; w1[k] = Wout[3*e+1]; w2[k] = Wout[3*e+2];
        bb[k] = bout[e];
    }

    if (t < OROWS){
        int bs = blockIdx.x*OROWS + t;
        float vs = g_sum[bs];
        float v0 = g_p0[bs], v1 = g_p1[bs], v2 = g_p2[bs];
        float4 rv = make_float4(0.f, 0.f, 0.f, 0.f);
        // present <=> any accumulator touched (exact-0 for present segment is
        // measure-zero: sums of hundreds of random nonzero terms)
        if (vs != 0.f || v0 != 0.f || v1 != 0.f || v2 != 0.f){
            float D   = (float)NPIX + vs;   // = sum(e) over seg + (NPIX-cnt)
            float inv = 1.0f / D;
            rv = make_float4(v0*inv, v1*inv, v2*inv, 1.0f);
        }
        srow[t] = rv;
        g_sum[bs] = 0.f; g_p0[bs] = 0.f; g_p1[bs] = 0.f; g_p2[bs] = 0.f;
    }
    __syncthreads();

    #pragma unroll
    for (int r = 0; r < OROWS; r++){
        float4 p = srow[r];
        float* o = out + (size_t)(blockIdx.x*OROWS + r)*EE;
        #pragma unroll
        for (int k = 0; k < 6; k++){
            // invalid row => p=(0,0,0,0) -> exact 0 (bias suppressed)
            o[t + k*128] = fmaf(p.x, w0[k], fmaf(p.y, w1[k], fmaf(p.z, w2[k], p.w*bb[k])));
        }
    }
}

extern "C" void kernel_launch(void* const* d_in, const int* in_sizes, int n_in,
                              void* d_out, int out_size) {
    const float* img  = (const float*)d_in[0];   // [8,3,224,224]
    const float* Wseg = (const float*)d_in[1];   // [196,3]
    const float* bseg = (const float*)d_in[2];   // [196]
    const float* wq   = (const float*)d_in[3];   // [3]
    const float* Wout = (const float*)d_in[4];   // [768,3]
    const float* bout = (const float*)d_in[5];   // [768]
    float* out = (float*)d_out;                  // [8,196,768]

    dim3 g(NBLK, BN);                            // 784 blocks
    k_main<<<g, TPB>>>(img, Wseg, bseg, wq);
    k_out<<<(BN*SS)/OROWS, 128>>>(Wout, bout, out);   // 196 blocks
}